// round 2
// baseline (speedup 1.0000x reference)
#include <cuda_runtime.h>

#define NN 50000
#define DD 128
#define ED 32
#define ET 800000
#define BN_EPS 1e-5f

// ---------------- scratch (device globals; no allocation allowed) ----------------
__device__ float g_h[NN * DD];        // (1+eps)*x + scatter-add target, then GEMM1 input
__device__ float g_y1[NN * DD];       // GEMM1 output (pre-BN)
__device__ float g_stats[4 * DD];     // [sum1 | sq1 | sum2 | sq2]
__device__ float g_bn[4 * DD];        // [scale1 | shift1 | scale2 | shift2]

// ---------------- helpers ----------------
__device__ __forceinline__ void ffma2(unsigned long long &d, unsigned long long a, unsigned long long b) {
    asm volatile("fma.rn.f32x2 %0, %1, %2, %0;" : "+l"(d) : "l"(a), "l"(b));
}
__device__ __forceinline__ unsigned long long pack2(float x) {
    unsigned long long r;
    asm("mov.b64 %0, {%1, %1};" : "=l"(r) : "f"(x));
    return r;
}
__device__ __forceinline__ float2 unpack2(unsigned long long v) {
    float2 f;
    asm("mov.b64 {%0, %1}, %2;" : "=f"(f.x), "=f"(f.y) : "l"(v));
    return f;
}
__device__ __forceinline__ void red_v4(float *p, float4 v) {
    asm volatile("red.global.add.v4.f32 [%0], {%1, %2, %3, %4};"
                 :: "l"(p), "f"(v.x), "f"(v.y), "f"(v.z), "f"(v.w) : "memory");
}

// ---------------- kernel 1: h = (1+eps)*x ; zero ALL stats ----------------
__global__ void k_init(const float *__restrict__ x, const float *__restrict__ eps) {
    int i = blockIdx.x * blockDim.x + threadIdx.x;
    float s = 1.0f + eps[0];
    if (i < NN * DD / 4) {
        float4 v = reinterpret_cast<const float4 *>(x)[i];
        v.x *= s; v.y *= s; v.z *= s; v.w *= s;
        reinterpret_cast<float4 *>(g_h)[i] = v;
    }
    if (blockIdx.x == 0) {
        for (int t = threadIdx.x; t < 4 * DD; t += 256) g_stats[t] = 0.0f;  // all 512!
    }
}

// ---------------- kernel 2: edge embed + gather + scatter-add ----------------
// block = 256 thr (8 warps). Tile = 64 edges. Each warp computes 8 edges,
// lane l owns output cols [4l, 4l+3]. We in smem (LDS.128 per k, amortized over
// 8 edges), edge_attr staged duplicated as float2 pairs so an LDS.64 broadcast
// yields a ready-packed {a,a} operand for fma.rn.f32x2.
__global__ __launch_bounds__(256) void k_edge(
    const float *__restrict__ x, const int *__restrict__ ei,
    const float *__restrict__ ea, const float *__restrict__ We,
    const float *__restrict__ be)
{
    __shared__ __align__(16) float we_s[ED * DD];     // 16 KB, [k][n]
    __shared__ __align__(16) float2 ea_s[64 * ED];    // 16 KB, [e][k] duplicated pairs

    const int tid  = threadIdx.x;
    const int lane = tid & 31;
    const int warp = tid >> 5;

    for (int i = tid; i < ED * DD; i += 256) we_s[i] = We[i];

    const float4 be4 = reinterpret_cast<const float4 *>(be)[lane];
    const int ntiles = ET / 64;   // 12500, exact

    for (int tile = blockIdx.x; tile < ntiles; tile += gridDim.x) {
        const int ebase = tile * 64;
        __syncthreads();   // previous tile compute done (also orders we_s on 1st iter)
#pragma unroll
        for (int i = 0; i < 8; i++) {
            int idx = tid + i * 256;           // 64 edges * 32 k = 2048 values
            int e = idx >> 5, k = idx & 31;
            float v = ea[(long)(ebase + e) * ED + k];
            ea_s[e * ED + k] = make_float2(v, v);
        }
        __syncthreads();

        unsigned long long a01[8], a23[8];
#pragma unroll
        for (int e = 0; e < 8; e++) { a01[e] = 0ull; a23[e] = 0ull; }

        const int ew = warp * 8;
#pragma unroll
        for (int k = 0; k < ED; k++) {
            ulonglong2 w = reinterpret_cast<const ulonglong2 *>(we_s)[k * 32 + lane];
#pragma unroll
            for (int e = 0; e < 8; e++) {
                unsigned long long a2 =
                    *reinterpret_cast<const unsigned long long *>(&ea_s[(ew + e) * ED + k]);
                ffma2(a01[e], a2, w.x);
                ffma2(a23[e], a2, w.y);
            }
        }

#pragma unroll
        for (int e = 0; e < 8; e++) {
            int eg = ebase + ew + e;
            int s  = __ldg(&ei[eg]);
            int d  = __ldg(&ei[ET + eg]);
            float2 f01 = unpack2(a01[e]);
            float2 f23 = unpack2(a23[e]);
            float4 xv = *reinterpret_cast<const float4 *>(&x[(long)s * DD + lane * 4]);
            float4 m;
            m.x = xv.x + fmaxf(f01.x + be4.x, 0.0f);
            m.y = xv.y + fmaxf(f01.y + be4.y, 0.0f);
            m.z = xv.z + fmaxf(f23.x + be4.z, 0.0f);
            m.w = xv.w + fmaxf(f23.y + be4.w, 0.0f);
            red_v4(&g_h[(long)d * DD + lane * 4], m);
        }
    }
}

// ---------------- kernel 3/5: GEMM [NN,128]@[128,128] + bias + column stats -----
// PASS 0: A = g_h, Y = g_y1.  PASS 1: A = relu(bn1(g_y1)) applied on load, Y = out.
// block 256 thr = 16x16, thread tile 8x8, K tiled by 32, f32x2 accumulators.
template <int PASS>
__global__ __launch_bounds__(256) void k_gemm(
    const float *__restrict__ W, const float *__restrict__ bias, float *__restrict__ Yext)
{
    __shared__ __align__(16) float As[DD][36];   // [m][k] (+pad), 18 KB
    __shared__ __align__(16) float Ws[32][DD];   // [k][n], 16 KB
    __shared__ float cs[DD], cq[DD];

    const float *A = (PASS == 0) ? g_h : g_y1;
    float *Y       = (PASS == 0) ? g_y1 : Yext;

    const int tid = threadIdx.x;
    const int tx = tid & 15, ty = tid >> 4;
    const int rowBase = blockIdx.x * DD;

    unsigned long long acc[8][4];
#pragma unroll
    for (int i = 0; i < 8; i++)
#pragma unroll
        for (int j = 0; j < 4; j++) acc[i][j] = 0ull;

    for (int kt = 0; kt < DD; kt += 32) {
        __syncthreads();
#pragma unroll
        for (int i = 0; i < 4; i++) {              // A tile: 128 rows x 32 cols
            int idx = tid + i * 256;               // 1024 float4
            int m = idx >> 3, c = idx & 7;
            int row = rowBase + m;
            float4 v = make_float4(0.f, 0.f, 0.f, 0.f);
            if (row < NN)
                v = *reinterpret_cast<const float4 *>(&A[(long)row * DD + kt + c * 4]);
            if (PASS == 1) {
                float4 sc = *reinterpret_cast<const float4 *>(&g_bn[kt + c * 4]);
                float4 sh = *reinterpret_cast<const float4 *>(&g_bn[DD + kt + c * 4]);
                v.x = fmaxf(v.x * sc.x + sh.x, 0.0f);
                v.y = fmaxf(v.y * sc.y + sh.y, 0.0f);
                v.z = fmaxf(v.z * sc.z + sh.z, 0.0f);
                v.w = fmaxf(v.w * sc.w + sh.w, 0.0f);
            }
            *reinterpret_cast<float4 *>(&As[m][c * 4]) = v;
        }
#pragma unroll
        for (int i = 0; i < 4; i++) {              // W tile: 32 rows x 128 cols
            int idx = tid + i * 256;
            int r = idx >> 5, c = idx & 31;
            *reinterpret_cast<float4 *>(&Ws[r][c * 4]) =
                *reinterpret_cast<const float4 *>(&W[(long)(kt + r) * DD + c * 4]);
        }
        __syncthreads();

#pragma unroll
        for (int kk = 0; kk < 32; kk++) {
            ulonglong2 b0 = *reinterpret_cast<const ulonglong2 *>(&Ws[kk][tx * 8]);
            ulonglong2 b1 = *reinterpret_cast<const ulonglong2 *>(&Ws[kk][tx * 8 + 4]);
#pragma unroll
            for (int i = 0; i < 8; i++) {
                unsigned long long a2 = pack2(As[ty * 8 + i][kk]);
                ffma2(acc[i][0], a2, b0.x);
                ffma2(acc[i][1], a2, b0.y);
                ffma2(acc[i][2], a2, b1.x);
                ffma2(acc[i][3], a2, b1.y);
            }
        }
    }

    // epilogue: bias, store, per-column stats
    float4 bias0 = *reinterpret_cast<const float4 *>(&bias[tx * 8]);
    float4 bias1 = *reinterpret_cast<const float4 *>(&bias[tx * 8 + 4]);
    float bsum[8], bsq[8];
#pragma unroll
    for (int j = 0; j < 8; j++) { bsum[j] = 0.0f; bsq[j] = 0.0f; }

#pragma unroll
    for (int i = 0; i < 8; i++) {
        int row = rowBase + ty * 8 + i;
        if (row < NN) {
            float2 v0 = unpack2(acc[i][0]);
            float2 v1 = unpack2(acc[i][1]);
            float2 v2 = unpack2(acc[i][2]);
            float2 v3 = unpack2(acc[i][3]);
            float y0 = v0.x + bias0.x, y1v = v0.y + bias0.y;
            float y2 = v1.x + bias0.z, y3 = v1.y + bias0.w;
            float y4 = v2.x + bias1.x, y5 = v2.y + bias1.y;
            float y6 = v3.x + bias1.z, y7 = v3.y + bias1.w;
            *reinterpret_cast<float4 *>(&Y[(long)row * DD + tx * 8]) =
                make_float4(y0, y1v, y2, y3);
            *reinterpret_cast<float4 *>(&Y[(long)row * DD + tx * 8 + 4]) =
                make_float4(y4, y5, y6, y7);
            bsum[0] += y0; bsq[0] += y0 * y0;
            bsum[1] += y1v; bsq[1] += y1v * y1v;
            bsum[2] += y2; bsq[2] += y2 * y2;
            bsum[3] += y3; bsq[3] += y3 * y3;
            bsum[4] += y4; bsq[4] += y4 * y4;
            bsum[5] += y5; bsq[5] += y5 * y5;
            bsum[6] += y6; bsq[6] += y6 * y6;
            bsum[7] += y7; bsq[7] += y7 * y7;
        }
    }

    if (tid < DD) { cs[tid] = 0.0f; cq[tid] = 0.0f; }
    __syncthreads();
#pragma unroll
    for (int j = 0; j < 8; j++) {
        atomicAdd(&cs[tx * 8 + j], bsum[j]);
        atomicAdd(&cq[tx * 8 + j], bsq[j]);
    }
    __syncthreads();
    if (tid < DD) {
        atomicAdd(&g_stats[PASS * 2 * DD + tid], cs[tid]);
        atomicAdd(&g_stats[PASS * 2 * DD + DD + tid], cq[tid]);
    }
}

// ---------------- kernel 4/6: fold BN stats into scale/shift ----------------
template <int PASS>
__global__ void k_bn(const float *__restrict__ g, const float *__restrict__ beta) {
    int t = threadIdx.x;
    float mean = g_stats[PASS * 2 * DD + t] * (1.0f / NN);
    float var  = g_stats[PASS * 2 * DD + DD + t] * (1.0f / NN) - mean * mean;
    float sc = g[t] * rsqrtf(var + BN_EPS);
    g_bn[PASS * 2 * DD + t] = sc;
    g_bn[PASS * 2 * DD + DD + t] = beta[t] - mean * sc;
}

// ---------------- kernel 7: final BN + ReLU in place on d_out ----------------
__global__ void k_out(float *__restrict__ y) {
    int i = blockIdx.x * blockDim.x + threadIdx.x;
    if (i >= NN * DD / 4) return;
    float4 v = reinterpret_cast<float4 *>(y)[i];
    int c4 = i & 31;
    float4 sc = *reinterpret_cast<const float4 *>(&g_bn[2 * DD + c4 * 4]);
    float4 sh = *reinterpret_cast<const float4 *>(&g_bn[3 * DD + c4 * 4]);
    v.x = fmaxf(v.x * sc.x + sh.x, 0.0f);
    v.y = fmaxf(v.y * sc.y + sh.y, 0.0f);
    v.z = fmaxf(v.z * sc.z + sh.z, 0.0f);
    v.w = fmaxf(v.w * sc.w + sh.w, 0.0f);
    reinterpret_cast<float4 *>(y)[i] = v;
}

// ---------------- launch ----------------
extern "C" void kernel_launch(void *const *d_in, const int *in_sizes, int n_in,
                              void *d_out, int out_size)
{
    const float *x     = (const float *)d_in[0];
    const int   *ei    = (const int *)d_in[1];
    const float *ea    = (const float *)d_in[2];
    const float *eps   = (const float *)d_in[3];
    const float *We    = (const float *)d_in[4];
    const float *be    = (const float *)d_in[5];
    const float *W1    = (const float *)d_in[6];
    const float *b1    = (const float *)d_in[7];
    const float *g1    = (const float *)d_in[8];
    const float *beta1 = (const float *)d_in[9];
    const float *W2    = (const float *)d_in[10];
    const float *b2    = (const float *)d_in[11];
    const float *g2    = (const float *)d_in[12];
    const float *beta2 = (const float *)d_in[13];
    float *out = (float *)d_out;

    k_init<<<6250, 256>>>(x, eps);
    k_edge<<<1184, 256>>>(x, ei, ea, We, be);
    k_gemm<0><<<(NN + DD - 1) / DD, 256>>>(W1, b1, nullptr);
    k_bn<0><<<1, 128>>>(g1, beta1);
    k_gemm<1><<<(NN + DD - 1) / DD, 256>>>(W2, b2, out);
    k_bn<1><<<1, 128>>>(g2, beta2);
    k_out<<<6250, 256>>>(out);
}